// round 5
// baseline (speedup 1.0000x reference)
#include <cuda_runtime.h>
#include <math.h>

// Problem constants
#define H     128
#define G4H   512        // 4*H
#define NL    3
#define FC_N  400
#define L1_N  500
#define L2_N  63
#define STEPS 65536

__device__ __forceinline__ float sigmoidf_(float v) {
    return 1.0f / (1.0f + expf(-v));
}

// Single fused block: only the last timestep matters (state reset each step,
// output = out[-1:]). 6 dependent small matvecs chained in shared memory.
__global__ __launch_bounds__(512, 1)
void rnn_head_kernel(const float* __restrict__ inputs,
                     const float* __restrict__ W_ih,
                     const float* __restrict__ b_ih,
                     const float* __restrict__ b_hh,
                     const float* __restrict__ W_fc,
                     const float* __restrict__ b_fc,
                     const float* __restrict__ W_l1,
                     const float* __restrict__ b_l1,
                     const float* __restrict__ W_l2,
                     const float* __restrict__ b_l2,
                     float* __restrict__ out)
{
    __shared__ __align__(16) float x[H];        // current layer input / hidden
    __shared__ __align__(16) float buf[G4H];    // gates, then fc output (400)
    __shared__ __align__(16) float l1s[512];    // l1 output (500)

    const int t = threadIdx.x;

    // Load last-timestep input
    if (t < H) x[t] = inputs[(size_t)(STEPS - 1) * H + t];
    __syncthreads();

    // ---- 3 LSTM layers (h0 = c0 = 0, so W_hh contributes nothing) ----
    for (int l = 0; l < NL; ++l) {
        // gates[t] = W_ih[l][t,:] . x + b_ih + b_hh   (512 rows, 128-dot each)
        {
            const float4* wr = reinterpret_cast<const float4*>(
                W_ih + ((size_t)l * G4H + t) * H);
            const float4* xv = reinterpret_cast<const float4*>(x);
            float s = 0.0f;
#pragma unroll
            for (int k = 0; k < H / 4; ++k) {
                float4 w = wr[k];
                float4 v = xv[k];
                s += w.x * v.x + w.y * v.y + w.z * v.z + w.w * v.w;
            }
            buf[t] = s + b_ih[l * G4H + t] + b_hh[l * G4H + t];
        }
        __syncthreads();
        // pointwise cell: c = sig(i)*tanh(g); h = sig(o)*tanh(c)
        if (t < H) {
            float ig = buf[t];
            float gg = buf[2 * H + t];
            float og = buf[3 * H + t];
            float c  = sigmoidf_(ig) * tanhf(gg);
            x[t]     = sigmoidf_(og) * tanhf(c);   // x reads finished pre-sync
        }
        __syncthreads();
    }

    // ---- FC: 400 x 128 ----
    if (t < FC_N) {
        const float4* wr = reinterpret_cast<const float4*>(W_fc + (size_t)t * H);
        const float4* xv = reinterpret_cast<const float4*>(x);
        float s = 0.0f;
#pragma unroll
        for (int k = 0; k < H / 4; ++k) {
            float4 w = wr[k];
            float4 v = xv[k];
            s += w.x * v.x + w.y * v.y + w.z * v.z + w.w * v.w;
        }
        buf[t] = s + b_fc[t];
    }
    __syncthreads();

    // ---- L1: 500 x 400 ----
    if (t < L1_N) {
        const float4* wr = reinterpret_cast<const float4*>(W_l1 + (size_t)t * FC_N);
        const float4* fv = reinterpret_cast<const float4*>(buf);
        float s = 0.0f;
#pragma unroll 10
        for (int k = 0; k < FC_N / 4; ++k) {
            float4 w = wr[k];
            float4 v = fv[k];
            s += w.x * v.x + w.y * v.y + w.z * v.z + w.w * v.w;
        }
        l1s[t] = s + b_l1[t];
    }
    __syncthreads();

    // ---- L2: 63 x 500, 8-way split-K + warp-shuffle reduce ----
    {
        const int o = t >> 3;          // output index (0..63)
        const int p = t & 7;           // part index (0..7)
        float s = 0.0f;
        if (o < L2_N) {
            const int base = p * 63;                 // 8*63 = 504 >= 500
            const int n    = (base + 63 <= L2_N * 0 + 500) ? 63 : (500 - base);
            const float* wr = W_l2 + (size_t)o * 500 + base;
            for (int k = 0; k < n; ++k)
                s += wr[k] * l1s[base + k];
        }
        // reduce groups of 8 within the warp
        s += __shfl_down_sync(0xFFFFFFFFu, s, 4, 8);
        s += __shfl_down_sync(0xFFFFFFFFu, s, 2, 8);
        s += __shfl_down_sync(0xFFFFFFFFu, s, 1, 8);
        if (p == 0 && o < L2_N)
            out[o] = s + b_l2[o];
    }
}

extern "C" void kernel_launch(void* const* d_in, const int* in_sizes, int n_in,
                              void* d_out, int out_size) {
    const float* inputs = (const float*)d_in[0];
    const float* W_ih   = (const float*)d_in[1];
    // d_in[2] = W_hh — mathematically dead (h0 = 0)
    const float* b_ih   = (const float*)d_in[3];
    const float* b_hh   = (const float*)d_in[4];
    const float* W_fc   = (const float*)d_in[5];
    const float* b_fc   = (const float*)d_in[6];
    const float* W_l1   = (const float*)d_in[7];
    const float* b_l1   = (const float*)d_in[8];
    const float* W_l2   = (const float*)d_in[9];
    const float* b_l2   = (const float*)d_in[10];
    float* out = (float*)d_out;

    rnn_head_kernel<<<1, 512>>>(inputs, W_ih, b_ih, b_hh,
                                W_fc, b_fc, W_l1, b_l1, W_l2, b_l2, out);
}

// round 6
// speedup vs baseline: 2.0215x; 2.0215x over previous
#include <cuda_runtime.h>
#include <math.h>

#define H      128
#define STEPS  65536
#define NBLK   28

// Cross-stage scratch + sync (device globals: no allocation)
__device__ float g_gates[3][512];   // raw LSTM gate pre-activations per layer
__device__ float g_fc[400];
__device__ float g_l1[500];
__device__ int   g_cnt[5];          // 0,1,2: lstm layers; 3: fc; 4: l1

extern __shared__ float smw[];      // padded weight tile

__device__ __forceinline__ float sigmoidf_(float v) {
    return 1.0f / (1.0f + expf(-v));
}

__global__ __launch_bounds__(512, 1)
void fused_rnn(const float* __restrict__ inputs,
               const float* __restrict__ W_ih,
               const float* __restrict__ b_ih,
               const float* __restrict__ b_hh,
               const float* __restrict__ W_fc,
               const float* __restrict__ b_fc,
               const float* __restrict__ W_l1,
               const float* __restrict__ b_l1,
               const float* __restrict__ W_l2,
               const float* __restrict__ b_l2,
               float* __restrict__ out)
{
    __shared__ float xin[512];
    const int b = blockIdx.x;
    const int t = threadIdx.x;

    // ---- role decode ----
    int stage, layer = 0, rows, cols, row0, TPR, cpt, waitIdx, waitTgt, doneIdx;
    const float* wsrc;
    if (b < 12) {                      // LSTM layers, 4 blocks x 128 rows
        stage = 0; layer = b >> 2; int sub = b & 3;
        rows = 128; cols = 128; row0 = sub * 128;
        wsrc = W_ih + ((size_t)layer * 512 + row0) * 128;
        TPR = 4; cpt = 32;
        waitIdx = layer ? layer - 1 : -1; waitTgt = 4; doneIdx = layer;
    } else if (b < 16) {               // FC 400x128, 4 blocks x 100 rows
        stage = 1; int sub = b - 12;
        rows = 100; cols = 128; row0 = sub * 100;
        wsrc = W_fc + (size_t)row0 * 128;
        TPR = 4; cpt = 32;
        waitIdx = 2; waitTgt = 4; doneIdx = 3;
    } else if (b < 26) {               // L1 500x400, 10 blocks x 50 rows
        stage = 2; int sub = b - 16;
        rows = 50; cols = 400; row0 = sub * 50;
        wsrc = W_l1 + (size_t)row0 * 400;
        TPR = 8; cpt = 50;
        waitIdx = 3; waitTgt = 4; doneIdx = 4;
    } else {                           // L2 63x500, 2 blocks
        stage = 3; int sub = b - 26;
        rows = sub ? 31 : 32; cols = 500; row0 = sub * 32;
        wsrc = W_l2 + (size_t)row0 * 500;
        TPR = 16; cpt = 32;
        waitIdx = 4; waitTgt = 10; doneIdx = -1;
    }

    // ---- 1) stream weight tile into smem (all blocks in parallel: full-chip DRAM BW)
    // global tile is contiguous (full matrix width == cols). smem rows padded
    // by one float4 to de-bank-conflict the compute phase.
    const int c4      = cols >> 2;         // cols always /4
    const int stride4 = c4 + 1;
    const int total   = rows * c4;
    const float4* gsrc = reinterpret_cast<const float4*>(wsrc);
    float4*       sdst = reinterpret_cast<float4*>(smw);
    for (int i = t; i < total; i += 512) {
        int r = i / c4, c = i - r * c4;
        sdst[r * stride4 + c] = gsrc[i];
    }

    // ---- 2) wait for producer stage (thread 0 spins; loads above already in flight)
    if (waitIdx >= 0 && t == 0) {
        while (*(volatile int*)&g_cnt[waitIdx] < waitTgt)
            __nanosleep(64);
    }
    __syncthreads();   // tile stores complete + flag observed by all

    // ---- 3) build input vector in smem
    if (stage == 0 && layer == 0) {
        if (t < H) xin[t] = inputs[(size_t)(STEPS - 1) * H + t];
    } else if (stage == 0 || stage == 1) {
        // consume raw gates of LSTM layer (layer-1) or layer 2 (for FC)
        int src = (stage == 0) ? layer - 1 : 2;
        if (t < H) {
            float ig = g_gates[src][t];
            float gg = g_gates[src][t + 2 * H];
            float og = g_gates[src][t + 3 * H];
            float c  = sigmoidf_(ig) * tanhf(gg);     // f*c0 = 0
            xin[t]   = sigmoidf_(og) * tanhf(c);
        }
    } else if (stage == 2) {
        if (t < 400) xin[t] = g_fc[t];
    } else {
        if (t < 500) xin[t] = g_l1[t];
    }
    __syncthreads();

    // ---- 4) matvec: TPR threads per row, shfl-reduce
    const int row  = t / TPR;
    const int part = t - row * TPR;
    float s = 0.0f;
    if (row < rows) {
        const float* wr = smw + (size_t)row * (stride4 << 2);
        int k0 = part * cpt;
        int k1 = min(cols, k0 + cpt);
        #pragma unroll 8
        for (int k = k0; k < k1; ++k)
            s += wr[k] * xin[k];
    }
    #pragma unroll
    for (int off = TPR >> 1; off > 0; off >>= 1)
        s += __shfl_down_sync(0xFFFFFFFFu, s, off, TPR);

    if (part == 0 && row < rows) {
        int gr = row0 + row;
        if (stage == 0)
            g_gates[layer][gr] = s + b_ih[layer * 512 + gr] + b_hh[layer * 512 + gr];
        else if (stage == 1)
            g_fc[gr] = s + b_fc[gr];
        else if (stage == 2)
            g_l1[gr] = s + b_l1[gr];
        else
            out[gr] = s + b_l2[gr];
    }

    // ---- 5) publish
    if (doneIdx >= 0) {
        __syncthreads();
        __threadfence();
        if (t == 0) atomicAdd(&g_cnt[doneIdx], 1);
    }
}

extern "C" void kernel_launch(void* const* d_in, const int* in_sizes, int n_in,
                              void* d_out, int out_size) {
    const float* inputs = (const float*)d_in[0];
    const float* W_ih   = (const float*)d_in[1];
    // d_in[2] = W_hh — dead (h0 = 0)
    const float* b_ih   = (const float*)d_in[3];
    const float* b_hh   = (const float*)d_in[4];
    const float* W_fc   = (const float*)d_in[5];
    const float* b_fc   = (const float*)d_in[6];
    const float* W_l1   = (const float*)d_in[7];
    const float* b_l1   = (const float*)d_in[8];
    const float* W_l2   = (const float*)d_in[9];
    const float* b_l2   = (const float*)d_in[10];
    float* out = (float*)d_out;

    // reset stage counters (graph node, sequenced before the kernel)
    void* cntAddr = nullptr;
    cudaGetSymbolAddress(&cntAddr, g_cnt);
    cudaMemsetAsync(cntAddr, 0, 5 * sizeof(int));

    // largest tile: L1 stage = 50 * (400/4 + 1) * 16 B = 80800 B
    const int dynSmem = 50 * 101 * 16;
    cudaFuncSetAttribute(fused_rnn,
                         cudaFuncAttributeMaxDynamicSharedMemorySize, dynSmem);

    fused_rnn<<<NBLK, 512, dynSmem>>>(inputs, W_ih, b_ih, b_hh,
                                      W_fc, b_fc, W_l1, b_l1, W_l2, b_l2, out);
}

// round 7
// speedup vs baseline: 3.1585x; 1.5625x over previous
#include <cuda_runtime.h>
#include <math.h>

#define H      128
#define STEPS  65536
#define NBLK   42

// Cross-stage scratch + flags (device globals: no allocation).
// g_cnt is zero-initialized at module load and reset in-kernel each call.
__device__ float g_gates[3][512];   // raw LSTM gate pre-activations per layer
__device__ float g_fc[400];
__device__ float g_l1[512];
__device__ int   g_cnt[6];          // 0,1,2: lstm; 3: fc; 4: l1; 5: ack

__device__ __forceinline__ float sigmoidf_(float v) {
    return 1.0f / (1.0f + expf(-v));
}
__device__ __forceinline__ float dot4(float4 a, float4 b) {
    return a.x * b.x + a.y * b.y + a.z * b.z + a.w * b.w;
}
__device__ __forceinline__ int ld_relaxed(const int* p) {
    int v;
    asm volatile("ld.relaxed.gpu.b32 %0, [%1];" : "=r"(v) : "l"(p) : "memory");
    return v;
}
// All threads call; lane 0 of each warp polls, then acquire fence.
__device__ __forceinline__ void spin_ge(int* p, int tgt) {
    if ((threadIdx.x & 31) == 0) {
        while (ld_relaxed(p) < tgt) { }
    }
    __syncwarp();
    __threadfence();   // acquire: order subsequent reads of producer data
}

__global__ __launch_bounds__(512, 1)
void fused_rnn(const float* __restrict__ inputs,
               const float* __restrict__ W_ih,
               const float* __restrict__ b_ih,
               const float* __restrict__ b_hh,
               const float* __restrict__ W_fc,
               const float* __restrict__ b_fc,
               const float* __restrict__ W_l1,
               const float* __restrict__ b_l1,
               const float* __restrict__ W_l2,
               const float* __restrict__ b_l2,
               float* __restrict__ out)
{
    __shared__ __align__(16) float xin[512];
    const int b = blockIdx.x;
    const int t = threadIdx.x;

    // ================= LSTM stages: blocks 0-11 =================
    if (b < 12) {
        const int layer = b >> 2, sub = b & 3;
        const int row = t >> 2, p = t & 3;         // TPR=4, 128 rows/block
        const int gr = sub * 128 + row;
        // prefetch weights (8 independent LDG.128 -> MLP=8) + bias
        const float4* wr = reinterpret_cast<const float4*>(
            W_ih + ((size_t)layer * 512 + gr) * H) + p * 8;
        float4 w[8];
#pragma unroll
        for (int j = 0; j < 8; ++j) w[j] = wr[j];
        float bias = b_ih[layer * 512 + gr] + b_hh[layer * 512 + gr];

        if (layer == 0) {
            if (t < H) xin[t] = inputs[(size_t)(STEPS - 1) * H + t];
        } else {
            spin_ge(&g_cnt[layer - 1], 4);
            if (t < H) {
                float ig = g_gates[layer - 1][t];
                float gg = g_gates[layer - 1][t + 256];
                float og = g_gates[layer - 1][t + 384];
                float c  = sigmoidf_(ig) * tanhf(gg);     // f*c0 = 0
                xin[t]   = sigmoidf_(og) * tanhf(c);
            }
        }
        __syncthreads();

        const float4* xv = reinterpret_cast<const float4*>(xin) + p * 8;
        float s = 0.0f;
#pragma unroll
        for (int j = 0; j < 8; ++j) s += dot4(w[j], xv[j]);
        s += __shfl_down_sync(0xFFFFFFFFu, s, 2, 4);
        s += __shfl_down_sync(0xFFFFFFFFu, s, 1, 4);
        if (p == 0) g_gates[layer][gr] = s + bias;

        __syncthreads();
        if (t == 0) { __threadfence(); atomicAdd(&g_cnt[layer], 1); }
        return;
    }

    // ================= FC 400x128: blocks 12-19 =================
    if (b < 20) {
        const int sub = b - 12;
        const int row = t >> 3, p = t & 7;         // TPR=8, 50 rows/block
        const bool act = row < 50;
        const int gr = sub * 50 + row;
        float4 w[4] = {};
        float bias = 0.0f;
        if (act) {
            const float4* wr = reinterpret_cast<const float4*>(
                W_fc + (size_t)gr * H) + p * 4;
#pragma unroll
            for (int j = 0; j < 4; ++j) w[j] = wr[j];
            bias = b_fc[gr];
        }
        spin_ge(&g_cnt[2], 4);
        if (t < H) {
            float ig = g_gates[2][t];
            float gg = g_gates[2][t + 256];
            float og = g_gates[2][t + 384];
            float c  = sigmoidf_(ig) * tanhf(gg);
            xin[t]   = sigmoidf_(og) * tanhf(c);
        }
        __syncthreads();

        const float4* xv = reinterpret_cast<const float4*>(xin) + p * 4;
        float s = 0.0f;
#pragma unroll
        for (int j = 0; j < 4; ++j) s += dot4(w[j], xv[j]);
        s += __shfl_down_sync(0xFFFFFFFFu, s, 4, 8);
        s += __shfl_down_sync(0xFFFFFFFFu, s, 2, 8);
        s += __shfl_down_sync(0xFFFFFFFFu, s, 1, 8);
        if (p == 0 && act) g_fc[gr] = s + bias;

        __syncthreads();
        if (t == 0) { __threadfence(); atomicAdd(&g_cnt[3], 1); }
        return;
    }

    // ================= L1 500x400: blocks 20-39 =================
    if (b < 40) {
        const int sub = b - 20;
        const int row = t >> 4, p = t & 15;        // TPR=16, 25 rows/block
        const bool act = row < 25;
        const int gr = sub * 25 + row;
        // interleaved float4 chunks: c = p + j*16, c < 100
        float4 w[7] = {};
        float bias = 0.0f;
        if (act) {
            const float4* wb = reinterpret_cast<const float4*>(
                W_l1 + (size_t)gr * 400);
#pragma unroll
            for (int j = 0; j < 7; ++j) {
                int c = p + j * 16;
                if (c < 100) w[j] = wb[c];
            }
            bias = b_l1[gr];
        }
        spin_ge(&g_cnt[3], 8);
        if (t < 400) xin[t] = g_fc[t];
        __syncthreads();

        const float4* xv = reinterpret_cast<const float4*>(xin);
        float s = 0.0f;
#pragma unroll
        for (int j = 0; j < 7; ++j) {
            int c = p + j * 16;
            if (c < 100) s += dot4(w[j], xv[c]);
        }
        s += __shfl_down_sync(0xFFFFFFFFu, s, 8, 16);
        s += __shfl_down_sync(0xFFFFFFFFu, s, 4, 16);
        s += __shfl_down_sync(0xFFFFFFFFu, s, 2, 16);
        s += __shfl_down_sync(0xFFFFFFFFu, s, 1, 16);
        if (p == 0 && act) g_l1[gr] = s + bias;

        __syncthreads();
        if (t == 0) { __threadfence(); atomicAdd(&g_cnt[4], 1); }
        return;
    }

    // ================= L2 63x500: blocks 40-41 =================
    {
        const int sub = b - 40;
        const int rows = sub ? 31 : 32;
        const int row = t >> 4, p = t & 15;        // TPR=16
        const bool act = row < rows;
        const int gr = sub * 32 + row;
        // interleaved float2 chunks: c = p + j*16, c < 250 (row base 2000B: f2-aligned)
        float2 w[16] = {};
        float bias = 0.0f;
        if (act) {
            const float2* wb = reinterpret_cast<const float2*>(
                W_l2 + (size_t)gr * 500);
#pragma unroll
            for (int j = 0; j < 16; ++j) {
                int c = p + j * 16;
                if (c < 250) w[j] = wb[c];
            }
            bias = b_l2[gr];
        }
        spin_ge(&g_cnt[4], 20);
        if (t < 500) xin[t] = g_l1[t];
        __syncthreads();

        const float2* xv = reinterpret_cast<const float2*>(xin);
        float s = 0.0f;
#pragma unroll
        for (int j = 0; j < 16; ++j) {
            int c = p + j * 16;
            if (c < 250) { float2 x2 = xv[c]; s += w[j].x * x2.x + w[j].y * x2.y; }
        }
        s += __shfl_down_sync(0xFFFFFFFFu, s, 8, 16);
        s += __shfl_down_sync(0xFFFFFFFFu, s, 4, 16);
        s += __shfl_down_sync(0xFFFFFFFFu, s, 2, 16);
        s += __shfl_down_sync(0xFFFFFFFFu, s, 1, 16);
        if (p == 0 && act) out[gr] = s + bias;

        // in-kernel counter reset (replaces host-side memset graph node).
        // Safe: both L2 blocks passing the spin implies every earlier wait
        // has transitively passed and every atomicAdd is visible.
        __syncthreads();
        if (sub == 1 && t == 0) { __threadfence(); atomicAdd(&g_cnt[5], 1); }
        if (sub == 0 && t == 0) {
            while (ld_relaxed(&g_cnt[5]) < 1) { }
            volatile int* c = g_cnt;
#pragma unroll
            for (int i = 0; i < 6; ++i) c[i] = 0;
        }
    }
}

extern "C" void kernel_launch(void* const* d_in, const int* in_sizes, int n_in,
                              void* d_out, int out_size) {
    const float* inputs = (const float*)d_in[0];
    const float* W_ih   = (const float*)d_in[1];
    // d_in[2] = W_hh — dead (h0 = 0)
    const float* b_ih   = (const float*)d_in[3];
    const float* b_hh   = (const float*)d_in[4];
    const float* W_fc   = (const float*)d_in[5];
    const float* b_fc   = (const float*)d_in[6];
    const float* W_l1   = (const float*)d_in[7];
    const float* b_l1   = (const float*)d_in[8];
    const float* W_l2   = (const float*)d_in[9];
    const float* b_l2   = (const float*)d_in[10];
    float* out = (float*)d_out;

    fused_rnn<<<NBLK, 512>>>(inputs, W_ih, b_ih, b_hh,
                             W_fc, b_fc, W_l1, b_l1, W_l2, b_l2, out);
}